// round 6
// baseline (speedup 1.0000x reference)
#include <cuda_runtime.h>
#include <cuda_bf16.h>
#include <cstdint>

typedef unsigned long long ull;

// ===========================================================================
// mma.sync / ldmatrix / cp.async helpers (base sm_103 target — no tcgen05)
// ===========================================================================
__device__ __forceinline__ uint32_t smem_u32_of(const void* p) {
    uint32_t a;
    asm("{ .reg .u64 t; cvta.to.shared.u64 t, %1; cvt.u32.u64 %0, t; }"
        : "=r"(a) : "l"(p));
    return a;
}
__device__ __forceinline__ void ldsm4(uint32_t r[4], uint32_t addr) {
    asm volatile("ldmatrix.sync.aligned.m8n8.x4.shared.b16 {%0,%1,%2,%3}, [%4];"
        : "=r"(r[0]), "=r"(r[1]), "=r"(r[2]), "=r"(r[3]) : "r"(addr));
}
__device__ __forceinline__ void ldsm4t(uint32_t r[4], uint32_t addr) {
    asm volatile("ldmatrix.sync.aligned.m8n8.x4.trans.shared.b16 {%0,%1,%2,%3}, [%4];"
        : "=r"(r[0]), "=r"(r[1]), "=r"(r[2]), "=r"(r[3]) : "r"(addr));
}
__device__ __forceinline__ void mma16816(float c[4], const uint32_t a[4],
                                         const uint32_t b[2]) {
    asm volatile(
        "mma.sync.aligned.m16n8k16.row.col.f32.bf16.bf16.f32 "
        "{%0,%1,%2,%3}, {%4,%5,%6,%7}, {%8,%9}, {%0,%1,%2,%3};"
        : "+f"(c[0]), "+f"(c[1]), "+f"(c[2]), "+f"(c[3])
        : "r"(a[0]), "r"(a[1]), "r"(a[2]), "r"(a[3]), "r"(b[0]), "r"(b[1]));
}
__device__ __forceinline__ void cp16(uint32_t dst, const void* src) {
    asm volatile("cp.async.cg.shared.global [%0], [%1], 16;" :: "r"(dst), "l"(src));
}
#define CP_COMMIT() asm volatile("cp.async.commit_group;" ::: "memory")
template <int N>
__device__ __forceinline__ void cp_wait() {
    asm volatile("cp.async.wait_group %0;" :: "n"(N) : "memory");
}

// pack two floats into bf16x2 (lo = a, hi = b) + residual bf16x2
__device__ __forceinline__ void pack_split(float a, float b, uint32_t& hi, uint32_t& lo) {
    asm("cvt.rn.bf16x2.f32 %0, %1, %2;" : "=r"(hi) : "f"(b), "f"(a));
    float ha = __uint_as_float(hi << 16);
    float hb = __uint_as_float(hi & 0xffff0000u);
    float ra = a - ha, rb = b - hb;
    asm("cvt.rn.bf16x2.f32 %0, %1, %2;" : "=r"(lo) : "f"(rb), "f"(ra));
}

// ===========================================================================
// Problem constants
// ===========================================================================
#define BATCH   4
#define S_LEN   2048
#define EMB     1024
#define NHEAD   16
#define DHEAD   64
#define MROWS   (BATCH * S_LEN)   // 8192

// Scratch (device globals — allocations forbidden)
__device__ __nv_bfloat16 g_Ahi[MROWS * EMB];
__device__ __nv_bfloat16 g_Alo[MROWS * EMB];
__device__ __nv_bfloat16 g_Bhi[EMB * EMB];
__device__ __nv_bfloat16 g_Blo[EMB * EMB];
__device__ __nv_bfloat16 g_Qhi[MROWS * EMB];
__device__ __nv_bfloat16 g_Qlo[MROWS * EMB];
__device__ __nv_bfloat16 g_Khi[MROWS * EMB];
__device__ __nv_bfloat16 g_Klo[MROWS * EMB];
__device__ __nv_bfloat16 g_Vhi[MROWS * EMB];
__device__ __nv_bfloat16 g_Vlo[MROWS * EMB];
__device__ __nv_bfloat16 g_Chi[MROWS * EMB];
__device__ __nv_bfloat16 g_Clo[MROWS * EMB];
__device__ int g_idx[BATCH * S_LEN];
__device__ int g_cnt[BATCH];

// ===========================================================================
// Stable mask compaction
// ===========================================================================
__global__ __launch_bounds__(1024) void mask_compact_kernel(
    const int* __restrict__ mask, int* __restrict__ idx, int* __restrict__ cnt)
{
    const int b = blockIdx.x, t = threadIdx.x;
    const int wid = t >> 5, lane = t & 31;
    __shared__ int wsum[32], woff[32], chunk_total;
    int base = 0;
    #pragma unroll
    for (int half = 0; half < 2; half++) {
        int e = half * 1024 + t;
        int m = mask[b * S_LEN + e];
        unsigned bal = __ballot_sync(0xffffffffu, m != 0);
        int wtot = __popc(bal);
        int pos  = __popc(bal & ((1u << lane) - 1u));
        if (lane == 0) wsum[wid] = wtot;
        __syncthreads();
        if (t < 32) {
            int v = wsum[t], s = v;
            #pragma unroll
            for (int o = 1; o < 32; o <<= 1) {
                int u = __shfl_up_sync(0xffffffffu, s, o);
                if (t >= o) s += u;
            }
            woff[t] = s - v;
            if (t == 31) chunk_total = s;
        }
        __syncthreads();
        if (m) idx[b * S_LEN + base + woff[wid] + pos] = e;
        base += chunk_total;
        __syncthreads();
    }
    if (t == 0) cnt[b] = base;
}

// ===========================================================================
// fp32 -> (bf16 hi, bf16 lo) split conversion (dense)
// ===========================================================================
__global__ __launch_bounds__(256) void cvt_split_kernel(
    const float* __restrict__ x, __nv_bfloat16* __restrict__ hi,
    __nv_bfloat16* __restrict__ lo, int n4)
{
    int i = blockIdx.x * blockDim.x + threadIdx.x;
    if (i >= n4) return;
    float4 v = ((const float4*)x)[i];
    uint32_t h0, l0, h1, l1;
    pack_split(v.x, v.y, h0, l0);
    pack_split(v.z, v.w, h1, l1);
    ((uint2*)hi)[i] = make_uint2(h0, h1);
    ((uint2*)lo)[i] = make_uint2(l0, l1);
}

// ===========================================================================
// Row-gather + split cvt for K/V inputs
// ===========================================================================
__global__ __launch_bounds__(256) void cvt_gather_kernel(
    const float* __restrict__ src, const int* __restrict__ idx,
    const int* __restrict__ cnt,
    __nv_bfloat16* __restrict__ hi, __nv_bfloat16* __restrict__ lo)
{
    int i = blockIdx.x * blockDim.x + threadIdx.x;
    int rowq = i >> 8;
    int c4 = i & 255;
    int b = rowq >> 11, r = rowq & 2047;
    uint2 hh = make_uint2(0u, 0u), ll = make_uint2(0u, 0u);
    if (r < cnt[b]) {
        int s = idx[b * S_LEN + r];
        float4 v = ((const float4*)(src + ((size_t)(b * S_LEN + s)) * EMB))[c4];
        pack_split(v.x, v.y, hh.x, ll.x);
        pack_split(v.z, v.w, hh.y, ll.y);
    }
    ((uint2*)hi)[(size_t)rowq * 256 + c4] = hh;
    ((uint2*)lo)[(size_t)rowq * 256 + c4] = ll;
}

// ===========================================================================
// Split-bf16 3-term GEMM, 512 threads / 16 warps, warp tile 64x16.
// Term-major MMA ordering (independent accumulator sweeps), 1 barrier/chunk.
// ===========================================================================
#define CHUNKS 16
#define STG_BYTES 65536
#define NSTAGE 3
#define GSMEM (NSTAGE * STG_BYTES)

__global__ __launch_bounds__(512, 1) void gemm3_kernel(
    const __nv_bfloat16* __restrict__ Ahi, const __nv_bfloat16* __restrict__ Alo,
    const __nv_bfloat16* __restrict__ Bhi, const __nv_bfloat16* __restrict__ Blo,
    const float* __restrict__ bias, float* __restrict__ Cf,
    __nv_bfloat16* __restrict__ Chi, __nv_bfloat16* __restrict__ Clo,
    const int* __restrict__ counts)
{
    extern __shared__ __align__(1024) char smem[];
    const uint32_t sb = smem_u32_of(smem);
    const int t = threadIdx.x;
    const int bm = blockIdx.y * 128;
    const int bn = blockIdx.x * 128;

    if (counts && (bm & 2047) >= counts[bm >> 11]) return;

    const int w = t >> 5, lane = t & 31;
    const int wm = (w >> 3) * 64;       // 0 or 64
    const int wn = (w & 7) * 16;        // 0..112

    // loader: 2 x 16B per thread per 16KB array
    uint32_t lsw[2]; uint32_t lgo[2];
    #pragma unroll
    for (int i = 0; i < 2; i++) {
        int u = t + 512 * i;            // 0..1023
        int row = u >> 3, ku = u & 7;
        uint32_t off = row * 128 + ku * 16;
        lsw[i] = off ^ ((off >> 3) & 0x70);
        lgo[i] = (uint32_t)row * EMB + ku * 8;
    }
    const __nv_bfloat16* gAhi = Ahi + (size_t)bm * EMB;
    const __nv_bfloat16* gAlo = Alo + (size_t)bm * EMB;
    const __nv_bfloat16* gBhi = Bhi + (size_t)bn * EMB;
    const __nv_bfloat16* gBlo = Blo + (size_t)bn * EMB;

    const uint32_t xr  = (lane & 7) << 4;
    const uint32_t ak0 = (uint32_t)(lane & 16) ^ xr;
    const int      arow = lane & 15;
    const uint32_t bk0 = (uint32_t)((lane & 8) << 1) ^ xr;
    const int      brow = (lane & 7) | ((lane & 16) >> 1);
    uint32_t baA[4], baB;
    #pragma unroll
    for (int mi = 0; mi < 4; mi++)
        baA[mi] = (uint32_t)(wm + mi * 16 + arow) * 128 + ak0;
    baB = 32768u + (uint32_t)(wn + brow) * 128 + bk0;

    float acc[4][2][4];
    #pragma unroll
    for (int mi = 0; mi < 4; mi++)
        #pragma unroll
        for (int ni = 0; ni < 2; ni++)
            #pragma unroll
            for (int r = 0; r < 4; r++) acc[mi][ni][r] = 0.0f;

    auto load_chunk = [&](int c) {
        const uint32_t so = sb + (uint32_t)(c % NSTAGE) * STG_BYTES;
        const uint32_t ko = (uint32_t)c * 64;
        #pragma unroll
        for (int i = 0; i < 2; i++) {
            cp16(so +      0 + lsw[i], gAhi + lgo[i] + ko);
            cp16(so + 16384u + lsw[i], gAlo + lgo[i] + ko);
            cp16(so + 32768u + lsw[i], gBhi + lgo[i] + ko);
            cp16(so + 49152u + lsw[i], gBlo + lgo[i] + ko);
        }
        CP_COMMIT();
    };

    load_chunk(0);
    load_chunk(1);

    for (int c = 0; c < CHUNKS; c++) {
        if (c + 1 < CHUNKS) { cp_wait<1>(); } else { cp_wait<0>(); }
        __syncthreads();
        if (c + 2 < CHUNKS) load_chunk(c + 2);

        const uint32_t so = sb + (uint32_t)(c % NSTAGE) * STG_BYTES;
        #pragma unroll
        for (int ks = 0; ks < 4; ks++) {
            const uint32_t kx = (uint32_t)ks << 5;
            uint32_t ah[4][4], al[4][4], bh[4], bl[4];
            #pragma unroll
            for (int mi = 0; mi < 4; mi++) {
                ldsm4(ah[mi], so + (baA[mi] ^ kx));
                ldsm4(al[mi], so + 16384u + (baA[mi] ^ kx));
            }
            ldsm4(bh, so + (baB ^ kx));
            ldsm4(bl, so + 16384u + (baB ^ kx));
            // term-major sweeps: 8 independent accumulators per sweep
            #pragma unroll
            for (int mi = 0; mi < 4; mi++) {
                mma16816(acc[mi][0], ah[mi], &bh[0]);
                mma16816(acc[mi][1], ah[mi], &bh[2]);
            }
            #pragma unroll
            for (int mi = 0; mi < 4; mi++) {
                mma16816(acc[mi][0], al[mi], &bh[0]);
                mma16816(acc[mi][1], al[mi], &bh[2]);
            }
            #pragma unroll
            for (int mi = 0; mi < 4; mi++) {
                mma16816(acc[mi][0], ah[mi], &bl[0]);
                mma16816(acc[mi][1], ah[mi], &bl[2]);
            }
        }
    }

    // ---- epilogue ----
    #pragma unroll
    for (int mi = 0; mi < 4; mi++) {
        #pragma unroll
        for (int ni = 0; ni < 2; ni++) {
            int row = bm + wm + mi * 16 + (lane >> 2);
            int col = bn + wn + ni * 8 + (lane & 3) * 2;
            if (Cf) {
                float2 v0 = make_float2(acc[mi][ni][0], acc[mi][ni][1]);
                float2 v1 = make_float2(acc[mi][ni][2], acc[mi][ni][3]);
                if (bias) {
                    float b0 = __ldg(bias + col), b1 = __ldg(bias + col + 1);
                    v0.x += b0; v0.y += b1; v1.x += b0; v1.y += b1;
                }
                *(float2*)&Cf[(size_t)row * EMB + col] = v0;
                *(float2*)&Cf[(size_t)(row + 8) * EMB + col] = v1;
            } else {
                uint32_t hi, lo;
                pack_split(acc[mi][ni][0], acc[mi][ni][1], hi, lo);
                *(uint32_t*)&Chi[(size_t)row * EMB + col] = hi;
                *(uint32_t*)&Clo[(size_t)row * EMB + col] = lo;
                pack_split(acc[mi][ni][2], acc[mi][ni][3], hi, lo);
                *(uint32_t*)&Chi[(size_t)(row + 8) * EMB + col] = hi;
                *(uint32_t*)&Clo[(size_t)(row + 8) * EMB + col] = lo;
            }
        }
    }
}

// ===========================================================================
// Tensor-core flash attention over compacted keys.
// Term-major MMA ordering, 1 barrier per key tile.
// ===========================================================================
#define ASTG 32768
#define ANST 3
#define ASMEM (ANST * ASTG)

__global__ __launch_bounds__(256, 1) void attn_mma_kernel(
    const __nv_bfloat16* __restrict__ Qhi, const __nv_bfloat16* __restrict__ Qlo,
    const __nv_bfloat16* __restrict__ Khi, const __nv_bfloat16* __restrict__ Klo,
    const __nv_bfloat16* __restrict__ Vhi, const __nv_bfloat16* __restrict__ Vlo,
    const int* __restrict__ cnt,
    __nv_bfloat16* __restrict__ Chi, __nv_bfloat16* __restrict__ Clo)
{
    extern __shared__ __align__(1024) char smem[];
    const uint32_t sb = smem_u32_of(smem);
    const int t = threadIdx.x, w = t >> 5, lane = t & 31;
    const int qt = blockIdx.x, bh = blockIdx.y;
    const int b = bh >> 4, h = bh & 15;
    const int q0 = qt * 128;
    const int hcol = h * 64;
    const int n = cnt[b];
    const int ntiles = (n + 63) >> 6;

    // ---- stage Q, extract frags ----
    {
        const size_t qbase = ((size_t)(b * S_LEN + q0)) * EMB + hcol;
        #pragma unroll
        for (int i = 0; i < 8; i++) {
            int u = t + 256 * i;
            int arr = u >> 10;
            int r = (u >> 3) & 127;
            int du = u & 7;
            uint32_t off = r * 128 + du * 16;
            uint32_t sw = off ^ ((off >> 3) & 0x70);
            const __nv_bfloat16* src = (arr ? Qlo : Qhi) + qbase + (size_t)r * EMB + du * 8;
            cp16(sb + (uint32_t)arr * 16384u + sw, src);
        }
        CP_COMMIT();
    }
    cp_wait<0>();
    __syncthreads();

    uint32_t qh[4][4], ql[4][4];
    {
        uint32_t off = (uint32_t)(w * 16 + (lane & 15)) * 128 + ((lane >> 4) * 16);
        uint32_t baQ = off ^ ((off >> 3) & 0x70);
        #pragma unroll
        for (int k16 = 0; k16 < 4; k16++) {
            ldsm4(qh[k16], sb + (baQ ^ (uint32_t)(k16 * 32)));
            ldsm4(ql[k16], sb + 16384u + (baQ ^ (uint32_t)(k16 * 32)));
        }
    }
    __syncthreads();

    uint32_t baK, baV;
    {
        uint32_t keyk = (uint32_t)((lane & 7) | ((lane & 16) >> 1));
        uint32_t offk = keyk * 128 + (uint32_t)((lane & 8) << 1);
        baK = offk ^ ((offk >> 3) & 0x70);
        uint32_t keyv = (uint32_t)(lane & 15);
        uint32_t offv = keyv * 128 + (uint32_t)((lane >> 4) * 16);
        baV = offv ^ ((offv >> 3) & 0x70);
    }

    auto load_tile = [&](int kt, int stg) {
        const size_t gk = ((size_t)(b * S_LEN + kt * 64)) * EMB + hcol;
        const uint32_t sdst = sb + (uint32_t)stg * ASTG;
        #pragma unroll
        for (int i = 0; i < 8; i++) {
            int u = t + 256 * i;
            int arr = u >> 9;
            int r = (u >> 3) & 63;
            int du = u & 7;
            uint32_t off = r * 128 + du * 16;
            uint32_t sw = off ^ ((off >> 3) & 0x70);
            const __nv_bfloat16* p =
                (arr < 2) ? (arr ? Klo : Khi) : ((arr == 2) ? Vhi : Vlo);
            cp16(sdst + (uint32_t)arr * 8192u + sw, p + gk + (size_t)r * EMB + du * 8);
        }
        CP_COMMIT();
    };

    float O[8][4];
    #pragma unroll
    for (int j = 0; j < 8; j++)
        #pragma unroll
        for (int r = 0; r < 4; r++) O[j][r] = 0.0f;
    float m0 = -1e30f, m1 = -1e30f, l0 = 0.0f, l1 = 0.0f;

    if (ntiles == 0) {
        size_t row0 = (size_t)(b * S_LEN + q0 + w * 16 + (lane >> 2));
        #pragma unroll
        for (int j = 0; j < 8; j++) {
            int col = hcol + j * 8 + (lane & 3) * 2;
            *(uint32_t*)&Chi[row0 * EMB + col] = 0u;
            *(uint32_t*)&Clo[row0 * EMB + col] = 0u;
            *(uint32_t*)&Chi[(row0 + 8) * EMB + col] = 0u;
            *(uint32_t*)&Clo[(row0 + 8) * EMB + col] = 0u;
        }
        return;
    }

    load_tile(0, 0);
    if (ntiles > 1) load_tile(1, 1);

    for (int kt = 0; kt < ntiles; kt++) {
        if (kt + 1 < ntiles) { cp_wait<1>(); } else { cp_wait<0>(); }
        __syncthreads();
        if (kt + 2 < ntiles) load_tile(kt + 2, (kt + 2) % ANST);

        const uint32_t so = sb + (uint32_t)(kt % ANST) * ASTG;

        // ---- scores = Q K^T, term-major ----
        float sc[8][4];
        #pragma unroll
        for (int j = 0; j < 8; j++)
            #pragma unroll
            for (int r = 0; r < 4; r++) sc[j][r] = 0.0f;

        #pragma unroll
        for (int k16 = 0; k16 < 4; k16++) {
            const uint32_t kx = (uint32_t)(k16 * 32);
            uint32_t kh[4][4], kl[4][4];
            #pragma unroll
            for (int np = 0; np < 4; np++) {
                ldsm4(kh[np], so + ((baK + (uint32_t)np * 2048u) ^ kx));
                ldsm4(kl[np], so + 8192u + ((baK + (uint32_t)np * 2048u) ^ kx));
            }
            #pragma unroll
            for (int np = 0; np < 4; np++) {
                mma16816(sc[2 * np],     qh[k16], &kh[np][0]);
                mma16816(sc[2 * np + 1], qh[k16], &kh[np][2]);
            }
            #pragma unroll
            for (int np = 0; np < 4; np++) {
                mma16816(sc[2 * np],     ql[k16], &kh[np][0]);
                mma16816(sc[2 * np + 1], ql[k16], &kh[np][2]);
            }
            #pragma unroll
            for (int np = 0; np < 4; np++) {
                mma16816(sc[2 * np],     qh[k16], &kl[np][0]);
                mma16816(sc[2 * np + 1], qh[k16], &kl[np][2]);
            }
        }

        // ---- scale + boundary mask + online softmax ----
        const int c0 = (lane & 3) * 2;
        const int limit = n - kt * 64;
        float rm0 = m0, rm1 = m1;
        #pragma unroll
        for (int j = 0; j < 8; j++) {
            int kc = j * 8 + c0;
            bool v0 = kc < limit, v1 = kc + 1 < limit;
            sc[j][0] = v0 ? sc[j][0] * 0.125f : -1e10f;
            sc[j][1] = v1 ? sc[j][1] * 0.125f : -1e10f;
            sc[j][2] = v0 ? sc[j][2] * 0.125f : -1e10f;
            sc[j][3] = v1 ? sc[j][3] * 0.125f : -1e10f;
            rm0 = fmaxf(rm0, fmaxf(sc[j][0], sc[j][1]));
            rm1 = fmaxf(rm1, fmaxf(sc[j][2], sc[j][3]));
        }
        rm0 = fmaxf(rm0, __shfl_xor_sync(0xffffffffu, rm0, 1));
        rm0 = fmaxf(rm0, __shfl_xor_sync(0xffffffffu, rm0, 2));
        rm1 = fmaxf(rm1, __shfl_xor_sync(0xffffffffu, rm1, 1));
        rm1 = fmaxf(rm1, __shfl_xor_sync(0xffffffffu, rm1, 2));
        float corr0 = __expf(m0 - rm0);
        float corr1 = __expf(m1 - rm1);
        m0 = rm0; m1 = rm1;
        float ls0 = 0.0f, ls1 = 0.0f;
        #pragma unroll
        for (int j = 0; j < 8; j++) {
            sc[j][0] = __expf(sc[j][0] - m0);
            sc[j][1] = __expf(sc[j][1] - m0);
            sc[j][2] = __expf(sc[j][2] - m1);
            sc[j][3] = __expf(sc[j][3] - m1);
            ls0 += sc[j][0] + sc[j][1];
            ls1 += sc[j][2] + sc[j][3];
        }
        ls0 += __shfl_xor_sync(0xffffffffu, ls0, 1);
        ls0 += __shfl_xor_sync(0xffffffffu, ls0, 2);
        ls1 += __shfl_xor_sync(0xffffffffu, ls1, 1);
        ls1 += __shfl_xor_sync(0xffffffffu, ls1, 2);
        l0 = l0 * corr0 + ls0;
        l1 = l1 * corr1 + ls1;
        #pragma unroll
        for (int j = 0; j < 8; j++) {
            O[j][0] *= corr0; O[j][1] *= corr0;
            O[j][2] *= corr1; O[j][3] *= corr1;
        }

        // ---- pack P into split a-frags ----
        uint32_t ph[4][4], pl[4][4];
        #pragma unroll
        for (int kb = 0; kb < 4; kb++) {
            pack_split(sc[2 * kb][0],     sc[2 * kb][1],     ph[kb][0], pl[kb][0]);
            pack_split(sc[2 * kb][2],     sc[2 * kb][3],     ph[kb][1], pl[kb][1]);
            pack_split(sc[2 * kb + 1][0], sc[2 * kb + 1][1], ph[kb][2], pl[kb][2]);
            pack_split(sc[2 * kb + 1][2], sc[2 * kb + 1][3], ph[kb][3], pl[kb][3]);
        }

        // ---- O += P V, term-major, V via ldmatrix.trans ----
        #pragma unroll
        for (int kb = 0; kb < 4; kb++) {
            const uint32_t kadd = (uint32_t)kb * 2048u;
            uint32_t vh[4][4], vl[4][4];
            #pragma unroll
            for (int dp = 0; dp < 4; dp++) {
                const uint32_t dx = (uint32_t)(dp * 32);
                ldsm4t(vh[dp], so + 16384u + ((baV + kadd) ^ dx));
                ldsm4t(vl[dp], so + 24576u + ((baV + kadd) ^ dx));
            }
            #pragma unroll
            for (int dp = 0; dp < 4; dp++) {
                mma16816(O[2 * dp],     ph[kb], &vh[dp][0]);
                mma16816(O[2 * dp + 1], ph[kb], &vh[dp][2]);
            }
            #pragma unroll
            for (int dp = 0; dp < 4; dp++) {
                mma16816(O[2 * dp],     pl[kb], &vh[dp][0]);
                mma16816(O[2 * dp + 1], pl[kb], &vh[dp][2]);
            }
            #pragma unroll
            for (int dp = 0; dp < 4; dp++) {
                mma16816(O[2 * dp],     ph[kb], &vl[dp][0]);
                mma16816(O[2 * dp + 1], ph[kb], &vl[dp][2]);
            }
        }
    }

    // ---- epilogue ----
    float inv0 = 1.0f / l0, inv1 = 1.0f / l1;
    size_t row0 = (size_t)(b * S_LEN + q0 + w * 16 + (lane >> 2));
    size_t row1 = row0 + 8;
    #pragma unroll
    for (int j = 0; j < 8; j++) {
        int col = hcol + j * 8 + (lane & 3) * 2;
        uint32_t hi, lo;
        pack_split(O[j][0] * inv0, O[j][1] * inv0, hi, lo);
        *(uint32_t*)&Chi[row0 * EMB + col] = hi;
        *(uint32_t*)&Clo[row0 * EMB + col] = lo;
        pack_split(O[j][2] * inv1, O[j][3] * inv1, hi, lo);
        *(uint32_t*)&Chi[row1 * EMB + col] = hi;
        *(uint32_t*)&Clo[row1 * EMB + col] = lo;
    }
}

// ===========================================================================
// Launch
// ===========================================================================
extern "C" void kernel_launch(void* const* d_in, const int* in_sizes, int n_in,
                              void* d_out, int out_size)
{
    const float* q    = (const float*)d_in[0];
    const float* k    = (const float*)d_in[1];
    const float* v    = (const float*)d_in[2];
    const int*   mask = (const int*)  d_in[3];
    const float* Wq   = (const float*)d_in[4];
    const float* Wk   = (const float*)d_in[5];
    const float* Wv   = (const float*)d_in[6];
    const float* Wo   = (const float*)d_in[7];
    const float* bo   = (const float*)d_in[8];
    float* out = (float*)d_out;

    __nv_bfloat16 *Ahi, *Alo, *Bhi, *Blo;
    __nv_bfloat16 *Qhi, *Qlo, *Khi, *Klo, *Vhi, *Vlo, *Chi, *Clo;
    int *idx, *cnt;
    cudaGetSymbolAddress((void**)&Ahi, g_Ahi);
    cudaGetSymbolAddress((void**)&Alo, g_Alo);
    cudaGetSymbolAddress((void**)&Bhi, g_Bhi);
    cudaGetSymbolAddress((void**)&Blo, g_Blo);
    cudaGetSymbolAddress((void**)&Qhi, g_Qhi);
    cudaGetSymbolAddress((void**)&Qlo, g_Qlo);
    cudaGetSymbolAddress((void**)&Khi, g_Khi);
    cudaGetSymbolAddress((void**)&Klo, g_Klo);
    cudaGetSymbolAddress((void**)&Vhi, g_Vhi);
    cudaGetSymbolAddress((void**)&Vlo, g_Vlo);
    cudaGetSymbolAddress((void**)&Chi, g_Chi);
    cudaGetSymbolAddress((void**)&Clo, g_Clo);
    cudaGetSymbolAddress((void**)&idx, g_idx);
    cudaGetSymbolAddress((void**)&cnt, g_cnt);

    cudaFuncSetAttribute(gemm3_kernel,
                         cudaFuncAttributeMaxDynamicSharedMemorySize, GSMEM);
    cudaFuncSetAttribute(attn_mma_kernel,
                         cudaFuncAttributeMaxDynamicSharedMemorySize, ASMEM);

    const int nA4 = MROWS * EMB / 4;
    const int nW4 = EMB * EMB / 4;
    dim3 gGemm(EMB / 128, MROWS / 128);  // (8, 64)

    mask_compact_kernel<<<BATCH, 1024>>>(mask, idx, cnt);

    // Q projection
    cvt_split_kernel<<<(nA4 + 255) / 256, 256>>>(q, Ahi, Alo, nA4);
    cvt_split_kernel<<<(nW4 + 255) / 256, 256>>>(Wq, Bhi, Blo, nW4);
    gemm3_kernel<<<gGemm, 512, GSMEM>>>(Ahi, Alo, Bhi, Blo, nullptr, nullptr, Qhi, Qlo, nullptr);

    // K projection (compacted)
    cvt_gather_kernel<<<(nA4 + 255) / 256, 256>>>(k, idx, cnt, Ahi, Alo);
    cvt_split_kernel<<<(nW4 + 255) / 256, 256>>>(Wk, Bhi, Blo, nW4);
    gemm3_kernel<<<gGemm, 512, GSMEM>>>(Ahi, Alo, Bhi, Blo, nullptr, nullptr, Khi, Klo, cnt);

    // V projection (compacted)
    cvt_gather_kernel<<<(nA4 + 255) / 256, 256>>>(v, idx, cnt, Ahi, Alo);
    cvt_split_kernel<<<(nW4 + 255) / 256, 256>>>(Wv, Bhi, Blo, nW4);
    gemm3_kernel<<<gGemm, 512, GSMEM>>>(Ahi, Alo, Bhi, Blo, nullptr, nullptr, Vhi, Vlo, cnt);

    // attention
    dim3 gAttn(S_LEN / 128, BATCH * NHEAD);   // (16, 64)
    attn_mma_kernel<<<gAttn, 256, ASMEM>>>(Qhi, Qlo, Khi, Klo, Vhi, Vlo, cnt, Chi, Clo);

    // output projection (+bias)
    cvt_split_kernel<<<(nW4 + 255) / 256, 256>>>(Wo, Bhi, Blo, nW4);
    gemm3_kernel<<<gGemm, 512, GSMEM>>>(Chi, Clo, Bhi, Blo, bo, out, nullptr, nullptr, nullptr);
}